// round 2
// baseline (speedup 1.0000x reference)
#include <cuda_runtime.h>
#include <math.h>

// Problem constants (from reference)
#define D_M   1024
#define S_LEN 4096
#define B_SZ  8
#define N_ROWS (B_SZ * S_LEN)          // 32768
#define HALF_D (D_M / 2)               // 512

// inv_freq table, filled by init kernel in double precision each launch.
__device__ float g_inv_freq[HALF_D];

__global__ void pe_init_kernel() {
    int i = threadIdx.x;               // 0..511
    // inv_freq[i] = 10000^(-2*i/1024), computed in double, rounded to float.
    double e = -2.0 * (double)i / (double)D_M;
    g_inv_freq[i] = (float)pow(10000.0, e);
}

// One block per (b, s) row. 256 threads, each handles one float4 (4 floats).
__global__ void __launch_bounds__(256) emb_pe_kernel(
    const int*   __restrict__ x,       // [B*S] token ids (int32)
    const float* __restrict__ table,   // [VOCAB, D_M]
    float*       __restrict__ out)     // [B*S, D_M]
{
    const int row = blockIdx.x;                // 0..32767
    const int s   = row & (S_LEN - 1);         // position within sequence
    const int tok = __ldg(x + row);            // broadcast load

    const float4* __restrict__ src =
        reinterpret_cast<const float4*>(table + (size_t)tok * D_M);
    float4* __restrict__ dst =
        reinterpret_cast<float4*>(out + (size_t)row * D_M);

    const int t = threadIdx.x;                 // 0..255 -> d = 4t..4t+3

    float4 v = __ldg(src + t);

    const float pos = (float)s;
    const float f0 = g_inv_freq[2 * t + 0];
    const float f1 = g_inv_freq[2 * t + 1];

    float s0, c0, s1, c1;
    sincosf(pos * f0, &s0, &c0);
    sincosf(pos * f1, &s1, &c1);

    v.x += s0;   // d = 4t   (even -> sin of pair i=2t)
    v.y += c0;   // d = 4t+1 (odd  -> cos of pair i=2t)
    v.z += s1;   // d = 4t+2 (even -> sin of pair i=2t+1)
    v.w += c1;   // d = 4t+3 (odd  -> cos of pair i=2t+1)

    dst[t] = v;
}

extern "C" void kernel_launch(void* const* d_in, const int* in_sizes, int n_in,
                              void* d_out, int out_size) {
    const int*   x     = (const int*)d_in[0];      // [B*S] int32 token ids
    const float* table = (const float*)d_in[1];    // [VOCAB, D_M] fp32
    float*       out   = (float*)d_out;            // [B*S*D_M] fp32

    pe_init_kernel<<<1, HALF_D>>>();
    emb_pe_kernel<<<N_ROWS, 256>>>(x, table, out);
}

// round 8
// speedup vs baseline: 1.5081x; 1.5081x over previous
#include <cuda_runtime.h>

#define D_M    1024
#define S_LEN  4096
#define B_SZ   8
#define HALF_D (D_M / 2)   // 512

// ---------------------------------------------------------------------------
// Compile-time inv_freq table: invf[i] = 10000^(-2i/1024) = exp(-i*ln(1e4)/512)
// Computed in double precision via range-reduced Taylor at compile time, so it
// matches the (correctly-rounded) double pow -> float path that verified at
// rel_err 2.3e-8, with NO runtime init kernel.
// ---------------------------------------------------------------------------
constexpr double C_LN_1E4 = 9.210340371976182736071965818737456230; // ln(10000)
constexpr double C_LN2    = 0.693147180559945309417232121458176568; // ln(2)

constexpr double cexp(double x) {
    // x in [-9.3, 0]. Range-reduce: x = k*ln2 + r, |r| <= ln2/2.
    double q = x / C_LN2;
    int k = (int)(q >= 0.0 ? q + 0.5 : q - 0.5);
    double r = x - (double)k * C_LN2;
    // Taylor: exp(r) = sum r^n/n!, |r|<=0.347 -> term20 ~ 1e-25
    double term = 1.0, sum = 1.0;
    for (int n = 1; n <= 20; ++n) {
        term *= r / (double)n;
        sum += term;
    }
    // Scale by 2^k exactly (k <= 0 here).
    for (int j = 0; j < -k; ++j) sum *= 0.5;
    for (int j = 0; j <  k; ++j) sum *= 2.0;
    return sum;
}

struct alignas(16) InvFreqTbl { float v[HALF_D]; };

constexpr InvFreqTbl make_invf() {
    InvFreqTbl t{};
    for (int i = 0; i < HALF_D; ++i)
        t.v[i] = (float)cexp(-C_LN_1E4 * (double)i / (double)HALF_D);
    return t;
}

// __device__ global (L1-cached, coalesced float2 reads) -- NOT __constant__,
// whose cache serializes on per-thread divergent indices.
__device__ const InvFreqTbl g_invf = make_invf();

// ---------------------------------------------------------------------------
// One block per sequence position s (grid = 4096, 256 threads).
// Each thread owns output columns 4t..4t+3, computes its sin/cos ONCE, and
// applies them to all B_SZ=8 gathered embedding rows (which share the PE).
// 8 independent LDG.128 per thread -> MLP=8 on the gather.
// ---------------------------------------------------------------------------
__global__ void __launch_bounds__(256) emb_pe_kernel(
    const int*   __restrict__ x,       // [B*S] token ids (int32)
    const float* __restrict__ table,   // [VOCAB, D_M]
    float*       __restrict__ out)     // [B*S, D_M]
{
    const int s = blockIdx.x;          // 0..4095
    const int t = threadIdx.x;         // 0..255 -> columns 4t..4t+3

    // PE for this thread's 4 columns (pairs i=2t, 2t+1)
    const float2 f = reinterpret_cast<const float2*>(g_invf.v)[t];
    const float pos = (float)s;
    float s0, c0, s1, c1;
    sincosf(pos * f.x, &s0, &c0);
    sincosf(pos * f.y, &s1, &c1);

    // Token ids for the 8 batch rows at this s (uniform broadcast loads).
    int tok[B_SZ];
#pragma unroll
    for (int b = 0; b < B_SZ; ++b)
        tok[b] = __ldg(x + b * S_LEN + s);

    // 8 independent gathers, batched up front for MLP.
    float4 v[B_SZ];
#pragma unroll
    for (int b = 0; b < B_SZ; ++b)
        v[b] = __ldg(reinterpret_cast<const float4*>(
                         table + (size_t)tok[b] * D_M) + t);

#pragma unroll
    for (int b = 0; b < B_SZ; ++b) {
        float4 o = v[b];
        o.x += s0;   // even col -> sin
        o.y += c0;   // odd  col -> cos
        o.z += s1;
        o.w += c1;
        reinterpret_cast<float4*>(
            out + ((size_t)b * S_LEN + s) * D_M)[t] = o;
    }
}

extern "C" void kernel_launch(void* const* d_in, const int* in_sizes, int n_in,
                              void* d_out, int out_size) {
    const int*   x     = (const int*)d_in[0];      // [B*S] int32 token ids
    const float* table = (const float*)d_in[1];    // [VOCAB, D_M] fp32
    float*       out   = (float*)d_out;            // [B*S*D_M] fp32

    emb_pe_kernel<<<S_LEN, 256>>>(x, table, out);
}